// round 16
// baseline (speedup 1.0000x reference)
#include <cuda_runtime.h>
typedef unsigned long long u64;

#define Bn 16
#define Cn 32
#define Sn 256
#define Mn 12
#define Rn 24
#define Ln 4
#define BCn (Bn*Cn)
#define WTN (Ln*Rn*Mn*Cn*Cn)
#define SS (Sn*Sn)

__device__ float g_h[(size_t)BCn*SS];
__device__ float g_Y[(size_t)Bn*Sn*Rn*Cn];    // [b][y][q][c], q<12 re, q>=12 im
__device__ u64   g_T2[(size_t)Bn*Sn*Cn*Mn];   // [b][y][o][k] {tr,ti}
__device__ float g_Wtr[WTN];
__device__ float g_Wti[WTN];
__device__ float g_trigF[Rn*128];             // folded: rows 0-11 cos(k w), 12-23 sin(k w), w<128
__device__ u64   g_tcF[Rn*Sn];                // {c,c} at ky(r)*h
__device__ u64   g_tsF[Rn*Sn];

__device__ __forceinline__ u64 pk2(float x, float y) {
    u64 r; asm("mov.b64 %0,{%1,%2};" : "=l"(r) : "f"(x), "f"(y)); return r;
}
__device__ __forceinline__ void up2(u64 a, float& x, float& y) {
    asm("mov.b64 {%0,%1},%2;" : "=f"(x), "=f"(y) : "l"(a));
}
__device__ __forceinline__ u64 f2fma(u64 a, u64 b, u64 c) {
    u64 d; asm("fma.rn.f32x2 %0,%1,%2,%3;" : "=l"(d) : "l"(a), "l"(b), "l"(c)); return d;
}

__global__ void k_setupA() {   // launch 0
    int q = blockIdx.x, w = threadIdx.x;
    if (w >= 128) return;
    int kq = (q < Mn) ? q : q - Mn;
    float s, c;
    sincospif((float)((kq*w) & 255) * (2.0f/256.0f), &s, &c);
    g_trigF[q*128 + w] = (q < Mn) ? c : s;
}
__global__ void k_setupB() {   // launch 1
    int q = blockIdx.x, w = threadIdx.x;
    int ky = (q < Mn) ? q : 232 + q;
    float s, c;
    sincospif((float)((ky*w) & 255) * (2.0f/256.0f), &s, &c);
    g_tcF[q*Sn + w] = pk2(c, c);
    g_tsF[q*Sn + w] = pk2(s, s);
}

__global__ void k_wt(const float* __restrict__ w1r, const float* __restrict__ w1i,
                     const float* __restrict__ w2r, const float* __restrict__ w2i) {
    int flat = blockIdx.x*256 + threadIdx.x;   // launch 2
    if (flat >= WTN) return;
    int o = flat & 31;
    int i = (flat >> 5) & 31;
    int k = (flat >> 10) % Mn;
    int r = (flat / (Mn*Cn*Cn)) % Rn;
    int l =  flat / (Rn*Mn*Cn*Cn);
    int ky = (r < Mn) ? r : r - Mn;
    size_t s = ((((size_t)l*Cn + i)*Cn + o)*Mn + ky)*Mn + k;
    const float sc = 1.0f/65536.0f;
    if (r < Mn) { g_Wtr[flat] = w1r[s]*sc; g_Wti[flat] = w1i[s]*sc; }
    else        { g_Wtr[flat] = w2r[s]*sc; g_Wti[flat] = w2i[s]*sc; }
}

// ---- k_modes: byte-identical to the 1038us version ----
__global__ void __launch_bounds__(768) k_modes(int l) {
    extern __shared__ u64 smu[];
    u64* sY = smu;              // [256][33] {re,im}
    u64* sZ = smu + 256*33;     // [c][25]
    u64* sO = sZ + 32*25;       // [o][25] padded to 33 rows
    int b = blockIdx.x / Mn, k = blockIdx.x % Mn;
    int t = threadIdx.x;
    const float* yb = g_Y + (size_t)b*Sn*Rn*Cn;
    for (int idx = t; idx < Cn*Sn; idx += 768) {
        int y = idx >> 5, c = idx & 31;
        const float* yp = yb + (size_t)y*(Rn*Cn) + k*Cn + c;
        sY[y*33 + c] = pk2(yp[0], yp[Mn*Cn]);
    }
    __syncthreads();
    int r = t >> 5, lane = t & 31;
    {
        u64 pm = (r & 1) ? pk2(-1.f, -1.f) : pk2(1.f, 1.f);
        const u64* tc = g_tcF + r*Sn;
        const u64* ts = g_tsF + r*Sn;
        u64 accP = 0, accQ = 0;
        #pragma unroll 4
        for (int hp = 0; hp < 128; hp++) {
            u64 ya = sY[hp*33 + lane];
            u64 yc = sY[(hp+128)*33 + lane];
            u64 u = f2fma(yc, pm, ya);
            accP = f2fma(u, __ldg(tc + hp), accP);
            accQ = f2fma(u, __ldg(ts + hp), accQ);
        }
        float px, py, qx, qy; up2(accP, px, py); up2(accQ, qx, qy);
        sZ[lane*25 + r] = pk2(px + qy, py - qx);
    }
    __syncthreads();
    {
        size_t wb = ((size_t)((l*Rn + r)*Mn + k))*(Cn*Cn) + lane;
        float orr = 0.f, oii = 0.f;
        #pragma unroll 8
        for (int i = 0; i < Cn; i++) {
            float zr, zi; up2(sZ[i*25 + r], zr, zi);
            float ar = __ldg(g_Wtr + wb + (size_t)i*Cn);
            float ai = __ldg(g_Wti + wb + (size_t)i*Cn);
            orr += zr*ar - zi*ai;
            oii += zr*ai + zi*ar;
        }
        sO[lane*25 + r] = pk2(orr, oii);
    }
    __syncthreads();
    {
        int h = t & 255, third = t >> 8;
        int o0 = third*11;
        int on = (third == 2) ? 10 : 11;
        u64 accP[11], accQ[11];
        #pragma unroll
        for (int i = 0; i < 11; i++) { accP[i] = 0; accQ[i] = 0; }
        for (int rr = 0; rr < Rn; rr++) {
            u64 c2 = __ldg(g_tcF + rr*Sn + h);
            u64 s2 = __ldg(g_tsF + rr*Sn + h);
            #pragma unroll
            for (int i = 0; i < 11; i++) {
                u64 O = sO[(o0 + i)*25 + rr];
                accP[i] = f2fma(O, c2, accP[i]);
                accQ[i] = f2fma(O, s2, accQ[i]);
            }
        }
        u64* Tb = g_T2 + ((size_t)(b*Sn + h)*Cn)*Mn + k;
        #pragma unroll
        for (int i = 0; i < 11; i++) if (i < on) {
            float px, py, qx, qy; up2(accP[i], px, py); up2(accQ[i], qx, qy);
            Tb[(size_t)(o0 + i)*Mn] = pk2(px - qy, qx + py);
        }
    }
}

// ---- k_layer: 1038us version, trig moved smem -> L1 (__ldg); 5 blocks/SM ----
template<int MODE>
__global__ void __launch_bounds__(256) k_layer(
    const float* __restrict__ x,
    const float* __restrict__ pw, const float* __restrict__ pb,
    const float* __restrict__ wsw, const float* __restrict__ wsb,
    const float* __restrict__ qw, const float* __restrict__ qb,
    int l, float* __restrict__ out)
{
    extern __shared__ u64 smu[];
    u64* s_wsu  = smu;                       // [32][16] {w[o][2i], w[o][2i+1]}
    u64* s_t12u = smu + 512;                 // [32][12] {tr,ti}
    float* s_v    = (float*)(smu + 896);     // [32][260]
    float* s_wb   = s_v + Cn*260;            // [32]
    float* s_qw   = s_wb + Cn;               // [32]

    int t = threadIdx.x;
    int b = blockIdx.x >> 8, y = blockIdx.x & 255;
    int w = t;
    float* hrow = g_h + (((size_t)b*Cn)*Sn + y)*Sn + w;

    u64 hin2[16];
    if (MODE >= 1) {
        #pragma unroll
        for (int i = 0; i < 16; i++)
            hin2[i] = pk2(hrow[(size_t)(2*i)*SS], hrow[(size_t)(2*i+1)*SS]);
    }

    if (MODE >= 1) {
        const u64* T2 = g_T2 + (size_t)blockIdx.x * (Cn*Mn);
        for (int i = t; i < Cn*Mn; i += 256) s_t12u[i] = T2[i];
        const float2* wsrc = (const float2*)(wsw + l*Cn*Cn);
        for (int i = t; i < Cn*16; i += 256) {
            float2 wv = wsrc[i];
            s_wsu[i] = pk2(wv.x, wv.y);
        }
        if (t < Cn) { s_wb[t] = wsb[l*Cn + t]; s_qw[t] = qw[t]; }
        __syncthreads();
    }

    if (MODE == 0) {
        float xin = x[(size_t)blockIdx.x*Sn + w];
        float gy = -1.f + (2.f/255.f)*(float)y;
        float gx = -1.f + (2.f/255.f)*(float)w;
        #pragma unroll 8
        for (int c = 0; c < Cn; c++) {
            float v = pw[c*3+0]*xin + pw[c*3+1]*gy + pw[c*3+2]*gx + pb[c];
            hrow[(size_t)c*SS] = v;
            s_v[c*260 + w] = v;
        }
    } else {
        u64 trig2[Mn];
        {
            int wl = w & 127;
            trig2[0] = pk2(1.f, 0.f);
            #pragma unroll
            for (int k = 1; k < Mn; k++) {
                float c = __ldg(g_trigF + k*128 + wl);
                float s = __ldg(g_trigF + (Mn + k)*128 + wl);
                float sg = ((w >> 7) & (k & 1)) ? -2.f : 2.f;
                trig2[k] = pk2(sg*c, -sg*s);
            }
        }
        float proj = 0.f;
        #pragma unroll 2
        for (int o = 0; o < Cn; o++) {
            const ulonglong2* wp = (const ulonglong2*)(s_wsu + o*16);
            u64 acc0 = pk2(s_wb[o], 0.f), acc1 = 0;
            #pragma unroll
            for (int j = 0; j < 8; j++) {
                ulonglong2 q2 = wp[j];
                acc0 = f2fma(hin2[2*j],   q2.x, acc0);
                acc1 = f2fma(hin2[2*j+1], q2.y, acc1);
            }
            const ulonglong2* tp = (const ulonglong2*)(s_t12u + o*12);
            u64 fac0 = 0, fac1 = 0;
            #pragma unroll
            for (int j = 0; j < 6; j++) {
                ulonglong2 tq = tp[j];
                fac0 = f2fma(tq.x, trig2[2*j],   fac0);
                fac1 = f2fma(tq.y, trig2[2*j+1], fac1);
            }
            float a0x, a0y, a1x, a1y, f0x, f0y, f1x, f1y;
            up2(acc0, a0x, a0y); up2(acc1, a1x, a1y);
            up2(fac0, f0x, f0y); up2(fac1, f1x, f1y);
            float v = (a0x + a0y) + (a1x + a1y) + (f0x + f0y) + (f1x + f1y);
            if (MODE == 1) {
                v = fmaxf(v, 0.f);
                hrow[(size_t)o*SS] = v;
                s_v[o*260 + w] = v;
            } else {
                proj += s_qw[o]*v;
            }
        }
        if (MODE == 2) {
            out[(size_t)blockIdx.x*Sn + w] = proj + qb[0];
            return;
        }
    }
    __syncthreads();

    // folded row-DFT, (3q, 2o) mapping: 128 active threads; trig via L1
    if (t < 128) {
        int m = t & 7, op = t >> 3;
        int q0 = 3*m, o0 = 2*op, o1 = o0 + 1;
        const float4* xlo0 = (const float4*)(s_v + o0*260);
        const float4* xhi0 = xlo0 + 32;
        const float4* xlo1 = (const float4*)(s_v + o1*260);
        const float4* xhi1 = xlo1 + 32;
        const float4* t0p = (const float4*)(g_trigF + q0*128);
        const float4* t1p = (const float4*)(g_trigF + (q0+1)*128);
        const float4* t2p = (const float4*)(g_trigF + (q0+2)*128);
        bool p0 = (q0 & 1);      // parity of q0 (and q0+2); q0+1 opposite
        float a00 = 0.f, a01 = 0.f, a02 = 0.f;
        float a10 = 0.f, a11 = 0.f, a12 = 0.f;
        #pragma unroll 4
        for (int w4 = 0; w4 < 32; w4++) {
            float4 lo0 = xlo0[w4], hi0 = xhi0[w4];
            float4 lo1 = xlo1[w4], hi1 = xhi1[w4];
            float4 e0, d0, e1, d1;
            e0.x = lo0.x + hi0.x; e0.y = lo0.y + hi0.y; e0.z = lo0.z + hi0.z; e0.w = lo0.w + hi0.w;
            d0.x = lo0.x - hi0.x; d0.y = lo0.y - hi0.y; d0.z = lo0.z - hi0.z; d0.w = lo0.w - hi0.w;
            e1.x = lo1.x + hi1.x; e1.y = lo1.y + hi1.y; e1.z = lo1.z + hi1.z; e1.w = lo1.w + hi1.w;
            d1.x = lo1.x - hi1.x; d1.y = lo1.y - hi1.y; d1.z = lo1.z - hi1.z; d1.w = lo1.w - hi1.w;
            float4 u0 = __ldg(t0p + w4), u1 = __ldg(t1p + w4), u2 = __ldg(t2p + w4);
            float4 s00 = p0 ? d0 : e0;
            float4 s01 = p0 ? e0 : d0;
            float4 s10 = p0 ? d1 : e1;
            float4 s11 = p0 ? e1 : d1;
            a00 += s00.x*u0.x + s00.y*u0.y + s00.z*u0.z + s00.w*u0.w;
            a01 += s01.x*u1.x + s01.y*u1.y + s01.z*u1.z + s01.w*u1.w;
            a02 += s00.x*u2.x + s00.y*u2.y + s00.z*u2.z + s00.w*u2.w;
            a10 += s10.x*u0.x + s10.y*u0.y + s10.z*u0.z + s10.w*u0.w;
            a11 += s11.x*u1.x + s11.y*u1.y + s11.z*u1.z + s11.w*u1.w;
            a12 += s10.x*u2.x + s10.y*u2.y + s10.z*u2.z + s10.w*u2.w;
        }
        float* yb = g_Y + (size_t)blockIdx.x*(Rn*Cn);
        float sg0 = (q0   >= Mn) ? -1.f : 1.f;       // Yi = -sum v*sin
        float sg1 = (q0+1 >= Mn) ? -1.f : 1.f;
        float sg2 = (q0+2 >= Mn) ? -1.f : 1.f;
        yb[(q0  )*Cn + o0] = sg0*a00;
        yb[(q0+1)*Cn + o0] = sg1*a01;
        yb[(q0+2)*Cn + o0] = sg2*a02;
        yb[(q0  )*Cn + o1] = sg0*a10;
        yb[(q0+1)*Cn + o1] = sg1*a11;
        yb[(q0+2)*Cn + o1] = sg2*a12;
    }
}

#define SMEM_LAYER (896*8 + (Cn*260 + 2*Cn)*4)
#define SMEM_MODES ((256*33 + 32*25 + 33*25)*8)

extern "C" void kernel_launch(void* const* d_in, const int* in_sizes, int n_in,
                              void* d_out, int out_size) {
    (void)in_sizes; (void)n_in; (void)out_size;
    const float* x    = (const float*)d_in[0];
    const float* p_w  = (const float*)d_in[1];
    const float* p_b  = (const float*)d_in[2];
    const float* ws_w = (const float*)d_in[3];
    const float* ws_b = (const float*)d_in[4];
    const float* w1r  = (const float*)d_in[5];
    const float* w1i  = (const float*)d_in[6];
    const float* w2r  = (const float*)d_in[7];
    const float* w2i  = (const float*)d_in[8];
    const float* q_w  = (const float*)d_in[9];
    const float* q_b  = (const float*)d_in[10];
    float* out = (float*)d_out;

    cudaFuncSetAttribute(k_layer<0>, cudaFuncAttributeMaxDynamicSharedMemorySize, SMEM_LAYER);
    cudaFuncSetAttribute(k_layer<1>, cudaFuncAttributeMaxDynamicSharedMemorySize, SMEM_LAYER);
    cudaFuncSetAttribute(k_layer<2>, cudaFuncAttributeMaxDynamicSharedMemorySize, SMEM_LAYER);
    cudaFuncSetAttribute(k_modes,    cudaFuncAttributeMaxDynamicSharedMemorySize, SMEM_MODES);

    k_setupA<<<Rn, Sn>>>();
    k_setupB<<<Rn, Sn>>>();
    k_wt<<<(WTN + 255)/256, 256>>>(w1r, w1i, w2r, w2i);
    k_layer<0><<<Bn*Sn, 256, SMEM_LAYER>>>(x, p_w, p_b, nullptr, nullptr, nullptr, nullptr, 0, out);
    for (int l = 0; l < Ln; l++) {
        k_modes<<<Bn*Mn, 768, SMEM_MODES>>>(l);
        if (l < Ln - 1)
            k_layer<1><<<Bn*Sn, 256, SMEM_LAYER>>>(nullptr, nullptr, nullptr,
                                                   ws_w, ws_b, q_w, q_b, l, out);
        else
            k_layer<2><<<Bn*Sn, 256, SMEM_LAYER>>>(nullptr, nullptr, nullptr,
                                                   ws_w, ws_b, q_w, q_b, l, out);
    }
}

// round 17
// speedup vs baseline: 1.5465x; 1.5465x over previous
#include <cuda_runtime.h>
typedef unsigned long long u64;

#define Bn 16
#define Cn 32
#define Sn 256
#define Mn 12
#define Rn 24
#define Ln 4
#define BCn (Bn*Cn)
#define WTN (Ln*Rn*Mn*Cn*Cn)
#define SS (Sn*Sn)

__device__ float g_h[(size_t)BCn*SS];
__device__ float g_Y[(size_t)Bn*Sn*Rn*Cn];    // [b][y][q][c], q<12 re, q>=12 im
__device__ u64   g_T2[(size_t)Bn*Sn*Cn*Mn];   // [b][y][o][k] {tr,ti}
__device__ float g_Wtr[WTN];
__device__ float g_Wti[WTN];
__device__ float g_trigF[Rn*128];             // folded: rows 0-11 cos(k w), 12-23 sin(k w), w<128
__device__ u64   g_tcF[Rn*Sn];                // {c,c} at ky(r)*h
__device__ u64   g_tsF[Rn*Sn];

__device__ __forceinline__ u64 pk2(float x, float y) {
    u64 r; asm("mov.b64 %0,{%1,%2};" : "=l"(r) : "f"(x), "f"(y)); return r;
}
__device__ __forceinline__ void up2(u64 a, float& x, float& y) {
    asm("mov.b64 {%0,%1},%2;" : "=f"(x), "=f"(y) : "l"(a));
}
__device__ __forceinline__ u64 f2fma(u64 a, u64 b, u64 c) {
    u64 d; asm("fma.rn.f32x2 %0,%1,%2,%3;" : "=l"(d) : "l"(a), "l"(b), "l"(c)); return d;
}

__global__ void k_setupA() {   // launch 0
    int q = blockIdx.x, w = threadIdx.x;
    if (w >= 128) return;
    int kq = (q < Mn) ? q : q - Mn;
    float s, c;
    sincospif((float)((kq*w) & 255) * (2.0f/256.0f), &s, &c);
    g_trigF[q*128 + w] = (q < Mn) ? c : s;
}
__global__ void k_setupB() {   // launch 1
    int q = blockIdx.x, w = threadIdx.x;
    int ky = (q < Mn) ? q : 232 + q;
    float s, c;
    sincospif((float)((ky*w) & 255) * (2.0f/256.0f), &s, &c);
    g_tcF[q*Sn + w] = pk2(c, c);
    g_tsF[q*Sn + w] = pk2(s, s);
}

__global__ void k_wt(const float* __restrict__ w1r, const float* __restrict__ w1i,
                     const float* __restrict__ w2r, const float* __restrict__ w2i) {
    int flat = blockIdx.x*256 + threadIdx.x;   // launch 2
    if (flat >= WTN) return;
    int o = flat & 31;
    int i = (flat >> 5) & 31;
    int k = (flat >> 10) % Mn;
    int r = (flat / (Mn*Cn*Cn)) % Rn;
    int l =  flat / (Rn*Mn*Cn*Cn);
    int ky = (r < Mn) ? r : r - Mn;
    size_t s = ((((size_t)l*Cn + i)*Cn + o)*Mn + ky)*Mn + k;
    const float sc = 1.0f/65536.0f;
    if (r < Mn) { g_Wtr[flat] = w1r[s]*sc; g_Wti[flat] = w1i[s]*sc; }
    else        { g_Wtr[flat] = w2r[s]*sc; g_Wti[flat] = w2i[s]*sc; }
}

// ---- k_modes: same math as 1038us version, 384 threads -> 2 blocks/SM, 1 wave ----
__global__ void __launch_bounds__(384, 2) k_modes(int l) {
    extern __shared__ u64 smu[];
    u64* sY = smu;              // [256][33] {re,im}
    u64* sZ = smu + 256*33;     // [c][25]
    u64* sO = sZ + 32*25;       // [o][25] padded to 33 rows
    int b = blockIdx.x / Mn, k = blockIdx.x % Mn;
    int t = threadIdx.x;
    const float* yb = g_Y + (size_t)b*Sn*Rn*Cn;
    for (int idx = t; idx < Cn*Sn; idx += 384) {
        int y = idx >> 5, c = idx & 31;
        const float* yp = yb + (size_t)y*(Rn*Cn) + k*Cn + c;
        sY[y*33 + c] = pk2(yp[0], yp[Mn*Cn]);
    }
    __syncthreads();
    int warp = t >> 5, lane = t & 31;      // 12 warps
    #pragma unroll
    for (int rp = 0; rp < 2; rp++) {       // stage B: r = warp, warp+12
        int r = warp + 12*rp;
        u64 pm = (r & 1) ? pk2(-1.f, -1.f) : pk2(1.f, 1.f);
        const u64* tc = g_tcF + r*Sn;
        const u64* ts = g_tsF + r*Sn;
        u64 accP = 0, accQ = 0;
        #pragma unroll 4
        for (int hp = 0; hp < 128; hp++) {
            u64 ya = sY[hp*33 + lane];
            u64 yc = sY[(hp+128)*33 + lane];
            u64 u = f2fma(yc, pm, ya);
            accP = f2fma(u, __ldg(tc + hp), accP);
            accQ = f2fma(u, __ldg(ts + hp), accQ);
        }
        float px, py, qx, qy; up2(accP, px, py); up2(accQ, qx, qy);
        sZ[lane*25 + r] = pk2(px + qy, py - qx);
    }
    __syncthreads();
    #pragma unroll
    for (int rp = 0; rp < 2; rp++) {       // mix: r = warp, warp+12
        int r = warp + 12*rp;
        size_t wb = ((size_t)((l*Rn + r)*Mn + k))*(Cn*Cn) + lane;
        float orr = 0.f, oii = 0.f;
        #pragma unroll 8
        for (int i = 0; i < Cn; i++) {
            float zr, zi; up2(sZ[i*25 + r], zr, zi);
            float ar = __ldg(g_Wtr + wb + (size_t)i*Cn);
            float ai = __ldg(g_Wti + wb + (size_t)i*Cn);
            orr += zr*ar - zi*ai;
            oii += zr*ai + zi*ar;
        }
        sO[lane*25 + r] = pk2(orr, oii);
    }
    __syncthreads();
    {   // inverse-H: third = t>>7 (o-range), two h passes
        int tt = t & 127, third = t >> 7;
        int o0 = third*11;
        int on = (third == 2) ? 10 : 11;
        #pragma unroll
        for (int hp2 = 0; hp2 < 2; hp2++) {
            int h = tt + 128*hp2;
            u64 accP[11], accQ[11];
            #pragma unroll
            for (int i = 0; i < 11; i++) { accP[i] = 0; accQ[i] = 0; }
            for (int rr = 0; rr < Rn; rr++) {
                u64 c2 = __ldg(g_tcF + rr*Sn + h);
                u64 s2 = __ldg(g_tsF + rr*Sn + h);
                #pragma unroll
                for (int i = 0; i < 11; i++) {
                    u64 O = sO[(o0 + i)*25 + rr];
                    accP[i] = f2fma(O, c2, accP[i]);
                    accQ[i] = f2fma(O, s2, accQ[i]);
                }
            }
            u64* Tb = g_T2 + ((size_t)(b*Sn + h)*Cn)*Mn + k;
            #pragma unroll
            for (int i = 0; i < 11; i++) if (i < on) {
                float px, py, qx, qy; up2(accP[i], px, py); up2(accQ[i], qx, qy);
                Tb[(size_t)(o0 + i)*Mn] = pk2(px - qy, qx + py);
            }
        }
    }
}

// ---- k_layer: byte-identical to the 1038us version ----
template<int MODE>
__global__ void __launch_bounds__(256) k_layer(
    const float* __restrict__ x,
    const float* __restrict__ pw, const float* __restrict__ pb,
    const float* __restrict__ wsw, const float* __restrict__ wsb,
    const float* __restrict__ qw, const float* __restrict__ qb,
    int l, float* __restrict__ out)
{
    extern __shared__ u64 smu[];
    u64* s_wsu  = smu;                       // [32][16] {w[o][2i], w[o][2i+1]}
    u64* s_t12u = smu + 512;                 // [32][12] {tr,ti}
    float* s_v    = (float*)(smu + 896);     // [32][260]
    float* s_trig = s_v + Cn*260;            // [24][132] folded
    float* s_wb   = s_trig + Rn*132;         // [32]
    float* s_qw   = s_wb + Cn;               // [32]

    int t = threadIdx.x;
    int b = blockIdx.x >> 8, y = blockIdx.x & 255;
    int w = t;
    float* hrow = g_h + (((size_t)b*Cn)*Sn + y)*Sn + w;

    u64 hin2[16];
    if (MODE >= 1) {
        #pragma unroll
        for (int i = 0; i < 16; i++)
            hin2[i] = pk2(hrow[(size_t)(2*i)*SS], hrow[(size_t)(2*i+1)*SS]);
    }

    for (int i = t; i < Rn*128; i += 256)
        s_trig[(i >> 7)*132 + (i & 127)] = g_trigF[i];
    if (MODE >= 1) {
        const u64* T2 = g_T2 + (size_t)blockIdx.x * (Cn*Mn);
        for (int i = t; i < Cn*Mn; i += 256) s_t12u[i] = T2[i];
        const float2* wsrc = (const float2*)(wsw + l*Cn*Cn);
        for (int i = t; i < Cn*16; i += 256) {
            float2 wv = wsrc[i];
            s_wsu[i] = pk2(wv.x, wv.y);
        }
        if (t < Cn) { s_wb[t] = wsb[l*Cn + t]; s_qw[t] = qw[t]; }
    }
    __syncthreads();

    if (MODE == 0) {
        float xin = x[(size_t)blockIdx.x*Sn + w];
        float gy = -1.f + (2.f/255.f)*(float)y;
        float gx = -1.f + (2.f/255.f)*(float)w;
        #pragma unroll 8
        for (int c = 0; c < Cn; c++) {
            float v = pw[c*3+0]*xin + pw[c*3+1]*gy + pw[c*3+2]*gx + pb[c];
            hrow[(size_t)c*SS] = v;
            s_v[c*260 + w] = v;
        }
    } else {
        u64 trig2[Mn];
        {
            int wl = w & 127;
            trig2[0] = pk2(1.f, 0.f);
            #pragma unroll
            for (int k = 1; k < Mn; k++) {
                float c = s_trig[k*132 + wl];
                float s = s_trig[(Mn + k)*132 + wl];
                float sg = ((w >> 7) & (k & 1)) ? -2.f : 2.f;
                trig2[k] = pk2(sg*c, -sg*s);
            }
        }
        float proj = 0.f;
        #pragma unroll 2
        for (int o = 0; o < Cn; o++) {
            const ulonglong2* wp = (const ulonglong2*)(s_wsu + o*16);
            u64 acc0 = pk2(s_wb[o], 0.f), acc1 = 0;
            #pragma unroll
            for (int j = 0; j < 8; j++) {
                ulonglong2 q2 = wp[j];
                acc0 = f2fma(hin2[2*j],   q2.x, acc0);
                acc1 = f2fma(hin2[2*j+1], q2.y, acc1);
            }
            const ulonglong2* tp = (const ulonglong2*)(s_t12u + o*12);
            u64 fac0 = 0, fac1 = 0;
            #pragma unroll
            for (int j = 0; j < 6; j++) {
                ulonglong2 tq = tp[j];
                fac0 = f2fma(tq.x, trig2[2*j],   fac0);
                fac1 = f2fma(tq.y, trig2[2*j+1], fac1);
            }
            float a0x, a0y, a1x, a1y, f0x, f0y, f1x, f1y;
            up2(acc0, a0x, a0y); up2(acc1, a1x, a1y);
            up2(fac0, f0x, f0y); up2(fac1, f1x, f1y);
            float v = (a0x + a0y) + (a1x + a1y) + (f0x + f0y) + (f1x + f1y);
            if (MODE == 1) {
                v = fmaxf(v, 0.f);
                hrow[(size_t)o*SS] = v;
                s_v[o*260 + w] = v;
            } else {
                proj += s_qw[o]*v;
            }
        }
        if (MODE == 2) {
            out[(size_t)blockIdx.x*Sn + w] = proj + qb[0];
            return;
        }
    }
    __syncthreads();

    // folded row-DFT, (3q, 2o) mapping: 128 active threads
    if (t < 128) {
        int m = t & 7, op = t >> 3;
        int q0 = 3*m, o0 = 2*op, o1 = o0 + 1;
        const float4* xlo0 = (const float4*)(s_v + o0*260);
        const float4* xhi0 = xlo0 + 32;
        const float4* xlo1 = (const float4*)(s_v + o1*260);
        const float4* xhi1 = xlo1 + 32;
        const float4* t0p = (const float4*)(s_trig + q0*132);
        const float4* t1p = (const float4*)(s_trig + (q0+1)*132);
        const float4* t2p = (const float4*)(s_trig + (q0+2)*132);
        bool p0 = (q0 & 1);
        float a00 = 0.f, a01 = 0.f, a02 = 0.f;
        float a10 = 0.f, a11 = 0.f, a12 = 0.f;
        #pragma unroll 4
        for (int w4 = 0; w4 < 32; w4++) {
            float4 lo0 = xlo0[w4], hi0 = xhi0[w4];
            float4 lo1 = xlo1[w4], hi1 = xhi1[w4];
            float4 e0, d0, e1, d1;
            e0.x = lo0.x + hi0.x; e0.y = lo0.y + hi0.y; e0.z = lo0.z + hi0.z; e0.w = lo0.w + hi0.w;
            d0.x = lo0.x - hi0.x; d0.y = lo0.y - hi0.y; d0.z = lo0.z - hi0.z; d0.w = lo0.w - hi0.w;
            e1.x = lo1.x + hi1.x; e1.y = lo1.y + hi1.y; e1.z = lo1.z + hi1.z; e1.w = lo1.w + hi1.w;
            d1.x = lo1.x - hi1.x; d1.y = lo1.y - hi1.y; d1.z = lo1.z - hi1.z; d1.w = lo1.w - hi1.w;
            float4 u0 = t0p[w4], u1 = t1p[w4], u2 = t2p[w4];
            float4 s00 = p0 ? d0 : e0;
            float4 s01 = p0 ? e0 : d0;
            float4 s10 = p0 ? d1 : e1;
            float4 s11 = p0 ? e1 : d1;
            a00 += s00.x*u0.x + s00.y*u0.y + s00.z*u0.z + s00.w*u0.w;
            a01 += s01.x*u1.x + s01.y*u1.y + s01.z*u1.z + s01.w*u1.w;
            a02 += s00.x*u2.x + s00.y*u2.y + s00.z*u2.z + s00.w*u2.w;
            a10 += s10.x*u0.x + s10.y*u0.y + s10.z*u0.z + s10.w*u0.w;
            a11 += s11.x*u1.x + s11.y*u1.y + s11.z*u1.z + s11.w*u1.w;
            a12 += s10.x*u2.x + s10.y*u2.y + s10.z*u2.z + s10.w*u2.w;
        }
        float* yb = g_Y + (size_t)blockIdx.x*(Rn*Cn);
        float sg0 = (q0   >= Mn) ? -1.f : 1.f;
        float sg1 = (q0+1 >= Mn) ? -1.f : 1.f;
        float sg2 = (q0+2 >= Mn) ? -1.f : 1.f;
        yb[(q0  )*Cn + o0] = sg0*a00;
        yb[(q0+1)*Cn + o0] = sg1*a01;
        yb[(q0+2)*Cn + o0] = sg2*a02;
        yb[(q0  )*Cn + o1] = sg0*a10;
        yb[(q0+1)*Cn + o1] = sg1*a11;
        yb[(q0+2)*Cn + o1] = sg2*a12;
    }
}

#define SMEM_LAYER (896*8 + (Cn*260 + Rn*132 + 2*Cn)*4)
#define SMEM_MODES ((256*33 + 32*25 + 33*25)*8)

extern "C" void kernel_launch(void* const* d_in, const int* in_sizes, int n_in,
                              void* d_out, int out_size) {
    (void)in_sizes; (void)n_in; (void)out_size;
    const float* x    = (const float*)d_in[0];
    const float* p_w  = (const float*)d_in[1];
    const float* p_b  = (const float*)d_in[2];
    const float* ws_w = (const float*)d_in[3];
    const float* ws_b = (const float*)d_in[4];
    const float* w1r  = (const float*)d_in[5];
    const float* w1i  = (const float*)d_in[6];
    const float* w2r  = (const float*)d_in[7];
    const float* w2i  = (const float*)d_in[8];
    const float* q_w  = (const float*)d_in[9];
    const float* q_b  = (const float*)d_in[10];
    float* out = (float*)d_out;

    cudaFuncSetAttribute(k_layer<0>, cudaFuncAttributeMaxDynamicSharedMemorySize, SMEM_LAYER);
    cudaFuncSetAttribute(k_layer<1>, cudaFuncAttributeMaxDynamicSharedMemorySize, SMEM_LAYER);
    cudaFuncSetAttribute(k_layer<2>, cudaFuncAttributeMaxDynamicSharedMemorySize, SMEM_LAYER);
    cudaFuncSetAttribute(k_modes,    cudaFuncAttributeMaxDynamicSharedMemorySize, SMEM_MODES);

    k_setupA<<<Rn, Sn>>>();
    k_setupB<<<Rn, Sn>>>();
    k_wt<<<(WTN + 255)/256, 256>>>(w1r, w1i, w2r, w2i);
    k_layer<0><<<Bn*Sn, 256, SMEM_LAYER>>>(x, p_w, p_b, nullptr, nullptr, nullptr, nullptr, 0, out);
    for (int l = 0; l < Ln; l++) {
        k_modes<<<Bn*Mn, 384, SMEM_MODES>>>(l);
        if (l < Ln - 1)
            k_layer<1><<<Bn*Sn, 256, SMEM_LAYER>>>(nullptr, nullptr, nullptr,
                                                   ws_w, ws_b, q_w, q_b, l, out);
        else
            k_layer<2><<<Bn*Sn, 256, SMEM_LAYER>>>(nullptr, nullptr, nullptr,
                                                   ws_w, ws_b, q_w, q_b, l, out);
    }
}